// round 11
// baseline (speedup 1.0000x reference)
#include <cuda_runtime.h>

// ---------------------------------------------------------------------------
// Problem constants
// ---------------------------------------------------------------------------
constexpr int Bb    = 4;
constexpr int Uu    = 64;
constexpr int Vv    = 256;
constexpr int BU    = Bb * Uu;     // 256
constexpr int BV    = Bb * Vv;     // 1024
constexpr int D     = 768;         // STATE_DIM == IN_DIM
constexpr int CD    = 384;         // CODE_DIM
constexpr int INNER = 512;         // NUM_HEADS * HEAD_DIM
constexpr int Hh    = 8;
constexpr int BKk   = 32;

// ---------------------------------------------------------------------------
// Scratch (device globals; no allocation allowed)
// ---------------------------------------------------------------------------
__device__ float g_MQ[BU * D];
__device__ float g_MK[BU * D];
__device__ float g_MV[BU * D];
__device__ float g_ME[BU * INNER];
__device__ float g_qmod[BU * D];
__device__ float g_Q[BU * INNER];
__device__ float g_Qp[3 * BU * INNER];     // G2 split-K partials
__device__ float g_sln[BV * D];
__device__ float g_A[BU * Hh * D];         // [(bu*8+h)][d]
__device__ float g_S[Bb * 512 * 256];      // [b][(u*8+h)][v]
__device__ float g_T[BU * Hh * D];         // [(bu*8+h)][d]
__device__ float g_msg[BU * INNER];
__device__ float g_msgp[2 * BU * INNER];   // G6 split-K partials
__device__ float g_outp[2 * BU * D];       // G7 split-K partials

// ---------------------------------------------------------------------------
// Double-buffered tiled fp32 GEMM core.
// C[r,c] = epi( sum_k A[r,k]*B[k,c], z, r, c )
// BT=true: B element (k,n) at B[n*ldb + k] (transposed access, coalesced on k).
// K multiple of 32; M,N multiples of BM,BN (true for all calls).
// ---------------------------------------------------------------------------
template <int BM, int BN, int NT, bool BT, class Epi>
__device__ __forceinline__ void gemm_core(
    const float* __restrict__ A, const float* __restrict__ B,
    float* __restrict__ C, int K, int lda, int ldb, int ldc,
    int z, int bm, int bn, Epi epi)
{
    constexpr int TX = 16, TY = NT / 16;
    constexpr int TM = BM / TY, TN = BN / TX;
    constexpr int RA = BM * BKk / NT, RB = BN * BKk / NT;
    static_assert(TM == 4, "A microtile must be float4");
    static_assert(TN == 4 || TN == 2, "B microtile float4/float2");

    __shared__ __align__(16) float As[2][BKk][BM + 4];
    __shared__ __align__(16) float Bs[2][BKk][BN + 4];

    const int tid = threadIdx.x;
    const int tx = tid % TX;
    const int ty = tid / TX;

    float ra[RA], rb[RB];
    float acc[TM][TN] = {};

    // ---- prologue: tile 0 global -> reg -> smem[0]
    #pragma unroll
    for (int i = 0; i < RA; ++i) {
        int idx = tid + i * NT;
        ra[i] = A[(long)(bm + idx / BKk) * lda + (idx % BKk)];
    }
    #pragma unroll
    for (int i = 0; i < RB; ++i) {
        int idx = tid + i * NT;
        if constexpr (BT) rb[i] = B[(long)(bn + idx / BKk) * ldb + (idx % BKk)];
        else              rb[i] = B[(long)(idx / BN) * ldb + bn + (idx % BN)];
    }
    #pragma unroll
    for (int i = 0; i < RA; ++i) {
        int idx = tid + i * NT;
        As[0][idx % BKk][idx / BKk] = ra[i];
    }
    #pragma unroll
    for (int i = 0; i < RB; ++i) {
        int idx = tid + i * NT;
        if constexpr (BT) Bs[0][idx % BKk][idx / BKk] = rb[i];
        else              Bs[0][idx / BN][idx % BN] = rb[i];
    }
    __syncthreads();

    const int nI = K / BKk;
    for (int it = 0; it < nI; ++it) {
        const int s = it & 1;

        // ---- prefetch tile it+1 into registers (overlaps with FMA block)
        if (it + 1 < nI) {
            const int k0 = (it + 1) * BKk;
            #pragma unroll
            for (int i = 0; i < RA; ++i) {
                int idx = tid + i * NT;
                ra[i] = A[(long)(bm + idx / BKk) * lda + k0 + (idx % BKk)];
            }
            #pragma unroll
            for (int i = 0; i < RB; ++i) {
                int idx = tid + i * NT;
                if constexpr (BT) rb[i] = B[(long)(bn + idx / BKk) * ldb + k0 + (idx % BKk)];
                else              rb[i] = B[(long)(k0 + idx / BN) * ldb + bn + (idx % BN)];
            }
        }

        // ---- compute from smem[s]
        #pragma unroll
        for (int k = 0; k < BKk; ++k) {
            float a4[TM], b4[TN];
            *(float4*)a4 = *(const float4*)&As[s][k][ty * TM];
            if constexpr (TN == 4)
                *(float4*)b4 = *(const float4*)&Bs[s][k][tx * TN];
            else
                *(float2*)b4 = *(const float2*)&Bs[s][k][tx * TN];
            #pragma unroll
            for (int i = 0; i < TM; ++i)
                #pragma unroll
                for (int j = 0; j < TN; ++j)
                    acc[i][j] = fmaf(a4[i], b4[j], acc[i][j]);
        }

        // ---- drain registers into smem[s^1]
        if (it + 1 < nI) {
            #pragma unroll
            for (int i = 0; i < RA; ++i) {
                int idx = tid + i * NT;
                As[s ^ 1][idx % BKk][idx / BKk] = ra[i];
            }
            #pragma unroll
            for (int i = 0; i < RB; ++i) {
                int idx = tid + i * NT;
                if constexpr (BT) Bs[s ^ 1][idx % BKk][idx / BKk] = rb[i];
                else              Bs[s ^ 1][idx / BN][idx % BN] = rb[i];
            }
        }
        __syncthreads();
    }

    #pragma unroll
    for (int i = 0; i < TM; ++i) {
        int r = bm + ty * TM + i;
        #pragma unroll
        for (int j = 0; j < TN; ++j) {
            int c = bn + tx * TN + j;
            C[(long)r * ldc + c] = epi(acc[i][j], z, r, c);
        }
    }
}

template <int BM, int BN, int NT, bool BT, class Epi>
__global__ void __launch_bounds__(NT)
gemm_k(const float* __restrict__ Ag, const float* __restrict__ Bg,
       float* __restrict__ Cg, int K, int lda, int ldb, int ldc,
       long sA, long sB, long sC, Epi epi)
{
    const int z = blockIdx.z;
    gemm_core<BM, BN, NT, BT, Epi>(Ag + (long)z * sA, Bg + (long)z * sB,
                                   Cg + (long)z * sC, K, lda, ldb, ldc,
                                   z, blockIdx.y * BM, blockIdx.x * BN, epi);
}

// ---------------------------------------------------------------------------
// Epilogues
// ---------------------------------------------------------------------------
struct EpiNone {
    __device__ float operator()(float a, int, int, int) const { return a; }
};
struct EpiScale {
    float s;
    __device__ float operator()(float a, int, int, int) const { return a * s; }
};
struct EpiMulRowMod {  // G3: * (1 + m[row*768 + col])
    const float* m;
    __device__ float operator()(float a, int, int r, int c) const {
        return a * (1.f + m[r * 768 + c]);
    }
};
struct EpiMulT {  // G5: * (1 + MV[bu*768 + d]); rows (u*8+h), batch b=z
    const float* mv;
    __device__ float operator()(float a, int z, int r, int c) const {
        int bu = z * 64 + (r >> 3);
        return a * (1.f + mv[bu * 768 + c]);
    }
};

// ---------------------------------------------------------------------------
// Merged modulation GEMM: A = codes, z selects (W, C, ldc). 32x64 tiles.
// grid (12, 8, 4); z=3 (Wme, N=512) uses only 8 x-blocks.
// ---------------------------------------------------------------------------
struct ModArgs {
    const float* W[4];
    float*       C[4];
    int          ld[4];
    int          nbx[4];
};

__global__ void __launch_bounds__(128)
modgemm_k(const float* __restrict__ codes, ModArgs ma)
{
    const int z = blockIdx.z;
    if ((int)blockIdx.x >= ma.nbx[z]) return;
    gemm_core<32, 64, 128, false, EpiNone>(
        codes, ma.W[z], ma.C[z], CD, CD, ma.ld[z], ma.ld[z],
        z, blockIdx.y * 32, blockIdx.x * 64, EpiNone{});
}

// ---------------------------------------------------------------------------
// G6 split-K wrapper: z encodes (head h, K-chunk ck).
// msg partials: P[ck][bu][h*64 + c], K chunk = 384.
// ---------------------------------------------------------------------------
__global__ void __launch_bounds__(128)
g6_k(const float* __restrict__ T, const float* __restrict__ Wv,
     float* __restrict__ P)
{
    const int h = blockIdx.z >> 1;
    const int ck = blockIdx.z & 1;
    gemm_core<32, 32, 128, false, EpiNone>(
        T + h * D + ck * 384,
        Wv + (long)ck * 384 * INNER + h * 64,
        P + (long)ck * (BU * INNER) + h * 64,
        384, Hh * D, INNER, INNER,
        0, blockIdx.y * 32, blockIdx.x * 32, EpiNone{});
}

// ---------------------------------------------------------------------------
// Split-K reduce kernels (deterministic, vectorized)
// ---------------------------------------------------------------------------
__global__ void __launch_bounds__(256)
reduce_q_k(const float* __restrict__ P, const float* __restrict__ bq,
           float* __restrict__ Q)
{
    int i = (blockIdx.x * 256 + threadIdx.x) * 4;        // < 131072
    float4 a = *(const float4*)(P + i);
    float4 b = *(const float4*)(P + i + BU * INNER);
    float4 c = *(const float4*)(P + i + 2 * BU * INNER);
    float4 bb = *(const float4*)(bq + (i & (INNER - 1)));
    float4 o;
    o.x = a.x + b.x + c.x + bb.x;
    o.y = a.y + b.y + c.y + bb.y;
    o.z = a.z + b.z + c.z + bb.z;
    o.w = a.w + b.w + c.w + bb.w;
    *(float4*)(Q + i) = o;
}

__global__ void __launch_bounds__(256)
reduce_msg_k(const float* __restrict__ P, const float* __restrict__ bv,
             const float* __restrict__ ME, float* __restrict__ msg)
{
    int i = (blockIdx.x * 256 + threadIdx.x) * 4;        // < 131072
    float4 a = *(const float4*)(P + i);
    float4 b = *(const float4*)(P + i + BU * INNER);
    float4 bb = *(const float4*)(bv + (i & (INNER - 1)));
    float4 m = *(const float4*)(ME + i);
    float4 o;
    o.x = (a.x + b.x + bb.x) * (1.f + m.x);
    o.y = (a.y + b.y + bb.y) * (1.f + m.y);
    o.z = (a.z + b.z + bb.z) * (1.f + m.z);
    o.w = (a.w + b.w + bb.w) * (1.f + m.w);
    *(float4*)(msg + i) = o;
}

__global__ void __launch_bounds__(256)
reduce_out_k(const float* __restrict__ P, const float* __restrict__ rec,
             const float* __restrict__ be, const float* __restrict__ gam,
             float* __restrict__ out)
{
    int i = (blockIdx.x * 256 + threadIdx.x) * 4;        // < 196608
    int col = i % D;                                     // 768 % 4 == 0
    float4 a = *(const float4*)(P + i);
    float4 b = *(const float4*)(P + i + BU * D);
    float4 r = *(const float4*)(rec + i);
    float4 e = *(const float4*)(be + col);
    float4 g = *(const float4*)(gam + col);
    float4 o;
    o.x = r.x + g.x * (a.x + b.x + e.x);
    o.y = r.y + g.y * (a.y + b.y + e.y);
    o.z = r.z + g.z * (a.z + b.z + e.z);
    o.w = r.w + g.w * (a.w + b.w + e.w);
    *(float4*)(out + i) = o;
}

// ---------------------------------------------------------------------------
// LayerNorm kernels (row = one 256-thread block, dim 768)
// ---------------------------------------------------------------------------
__device__ __forceinline__ void reduce2_768(float& s, float& s2)
{
    __shared__ float2 sm[8];
    #pragma unroll
    for (int o = 16; o; o >>= 1) {
        s  += __shfl_xor_sync(0xffffffffu, s,  o);
        s2 += __shfl_xor_sync(0xffffffffu, s2, o);
    }
    if ((threadIdx.x & 31) == 0) sm[threadIdx.x >> 5] = make_float2(s, s2);
    __syncthreads();
    s = 0.f; s2 = 0.f;
    #pragma unroll
    for (int i = 0; i < 8; ++i) { s += sm[i].x; s2 += sm[i].y; }
}

__global__ void ln_k(const float* __restrict__ xin, const float* __restrict__ g,
                     const float* __restrict__ bb, float* __restrict__ out)
{
    int row = blockIdx.x;
    const float* x = xin + (long)row * 768;
    float v[3], s = 0.f, s2 = 0.f;
    #pragma unroll
    for (int i = 0; i < 3; ++i) {
        v[i] = x[threadIdx.x + 256 * i];
        s += v[i]; s2 += v[i] * v[i];
    }
    reduce2_768(s, s2);
    float mu = s * (1.f / 768.f);
    float var = s2 * (1.f / 768.f) - mu * mu;
    float inv = rsqrtf(var + 1e-5f);
    #pragma unroll
    for (int i = 0; i < 3; ++i) {
        int d = threadIdx.x + 256 * i;
        out[(long)row * 768 + d] = (v[i] - mu) * inv * g[d] + bb[d];
    }
}

__global__ void ln_qmod_k(const float* __restrict__ rec, const float* __restrict__ g,
                          const float* __restrict__ bb, const float* __restrict__ MQ,
                          float* __restrict__ qmod)
{
    int row = blockIdx.x;
    const float* x = rec + (long)row * 768;
    float v[3], s = 0.f, s2 = 0.f;
    #pragma unroll
    for (int i = 0; i < 3; ++i) {
        v[i] = x[threadIdx.x + 256 * i];
        s += v[i]; s2 += v[i] * v[i];
    }
    reduce2_768(s, s2);
    float mu = s * (1.f / 768.f);
    float var = s2 * (1.f / 768.f) - mu * mu;
    float inv = rsqrtf(var + 1e-5f);
    #pragma unroll
    for (int i = 0; i < 3; ++i) {
        int d = threadIdx.x + 256 * i;
        float y = (v[i] - mu) * inv * g[d] + bb[d];
        qmod[(long)row * 768 + d] = y * (1.f + MQ[(long)row * 768 + d]);
    }
}

// ---------------------------------------------------------------------------
// Softmax over v (256) — one block per (b, u, h) row
// ---------------------------------------------------------------------------
__global__ void softmax_k(float* __restrict__ S)
{
    int row = blockIdx.x;
    float v = S[(long)row * 256 + threadIdx.x];
    __shared__ float sm[8];

    float m = v;
    #pragma unroll
    for (int o = 16; o; o >>= 1) m = fmaxf(m, __shfl_xor_sync(0xffffffffu, m, o));
    if ((threadIdx.x & 31) == 0) sm[threadIdx.x >> 5] = m;
    __syncthreads();
    m = sm[0];
    #pragma unroll
    for (int i = 1; i < 8; ++i) m = fmaxf(m, sm[i]);
    float e = __expf(v - m);
    __syncthreads();

    float su = e;
    #pragma unroll
    for (int o = 16; o; o >>= 1) su += __shfl_xor_sync(0xffffffffu, su, o);
    if ((threadIdx.x & 31) == 0) sm[threadIdx.x >> 5] = su;
    __syncthreads();
    su = 0.f;
    #pragma unroll
    for (int i = 0; i < 8; ++i) su += sm[i];

    S[(long)row * 256 + threadIdx.x] = e / su;
}

// ---------------------------------------------------------------------------
// Launch
// ---------------------------------------------------------------------------
static float* sym(const void* s)
{
    void* p = nullptr;
    cudaGetSymbolAddress(&p, s);
    return (float*)p;
}

extern "C" void kernel_launch(void* const* d_in, const int* in_sizes, int n_in,
                              void* d_out, int out_size)
{
    (void)in_sizes; (void)n_in; (void)out_size;

    const float* rec    = (const float*)d_in[0];
    const float* codes  = (const float*)d_in[1];
    const float* snd    = (const float*)d_in[2];
    const float* ln_r_g = (const float*)d_in[3];
    const float* ln_r_b = (const float*)d_in[4];
    const float* ln_s_g = (const float*)d_in[5];
    const float* ln_s_b = (const float*)d_in[6];
    const float* Wq  = (const float*)d_in[7];
    const float* bq  = (const float*)d_in[8];
    const float* Wmq = (const float*)d_in[9];
    const float* Wk  = (const float*)d_in[10];
    // d_in[11] = bk: constant over v -> softmax-invariant; intentionally unused
    const float* Wmk = (const float*)d_in[12];
    const float* Wv  = (const float*)d_in[13];
    const float* bv  = (const float*)d_in[14];
    const float* Wmv = (const float*)d_in[15];
    const float* We  = (const float*)d_in[16];
    const float* be  = (const float*)d_in[17];
    const float* Wme = (const float*)d_in[18];
    const float* gam = (const float*)d_in[19];
    float* out = (float*)d_out;

    float* MQ   = sym(g_MQ);
    float* MK   = sym(g_MK);
    float* MV   = sym(g_MV);
    float* ME   = sym(g_ME);
    float* qmod = sym(g_qmod);
    float* Q    = sym(g_Q);
    float* Qp   = sym(g_Qp);
    float* sln  = sym(g_sln);
    float* Aq   = sym(g_A);
    float* S    = sym(g_S);
    float* T    = sym(g_T);
    float* msg  = sym(g_msg);
    float* msgp = sym(g_msgp);
    float* outp = sym(g_outp);

    // G1 (merged): all 4 code modulations — 32x64 tiles, 368 active blocks
    ModArgs ma;
    ma.W[0] = Wmq; ma.W[1] = Wmk; ma.W[2] = Wmv; ma.W[3] = Wme;
    ma.C[0] = MQ;  ma.C[1] = MK;  ma.C[2] = MV;  ma.C[3] = ME;
    ma.ld[0] = D;  ma.ld[1] = D;  ma.ld[2] = D;  ma.ld[3] = INNER;
    ma.nbx[0] = 12; ma.nbx[1] = 12; ma.nbx[2] = 12; ma.nbx[3] = 8;
    modgemm_k<<<dim3(12, 8, 4), 128>>>(codes, ma);

    // LayerNorms
    ln_k<<<BV, 256>>>(snd, ln_s_g, ln_s_b, sln);
    ln_qmod_k<<<BU, 256>>>(rec, ln_r_g, ln_r_b, MQ, qmod);

    // G2 split-K3: Q partials = qmod @ Wq (K chunks of 256) — 384 blocks
    gemm_k<32, 32, 128, false><<<dim3(16, 8, 3), 128>>>(
        qmod, Wq, Qp, 256, D, INNER, INNER,
        256, (long)256 * INNER, (long)BU * INNER, EpiNone{});
    reduce_q_k<<<128, 256>>>(Qp, bq, Q);

    // G3: A[bu,h,d] = (Q_h . Wk_h^T)[d] * (1+MK); batched h=z — 768 blocks
    gemm_k<32, 64, 128, true><<<dim3(12, 8, Hh), 128>>>(
        Q, Wk, Aq, 64, INNER, INNER, Hh * D, 64, 64, D, EpiMulRowMod{MK});

    // G4: scores = A_b @ sln_b^T / 8; batched b=z — 512 blocks (32x32)
    gemm_k<32, 32, 128, true><<<dim3(8, 16, Bb), 128>>>(
        Aq, sln, S, D, D, D, 256,
        (long)512 * D, (long)Vv * D, (long)512 * 256, EpiScale{0.125f});

    softmax_k<<<Bb * 512, 256>>>(S);

    // G5: T = W_b @ sln_b, * (1+MV); batched b=z — 1536 blocks (32x32)
    gemm_k<32, 32, 128, false><<<dim3(24, 16, Bb), 128>>>(
        S, sln, T, Vv, 256, D, D,
        (long)512 * 256, (long)Vv * D, (long)512 * D, EpiMulT{MV});

    // G6 split-K2 per head: msg partials — 256 blocks
    g6_k<<<dim3(2, 8, 16), 128>>>(T, Wv, msgp);
    reduce_msg_k<<<128, 256>>>(msgp, bv, ME, msg);

    // G7 split-K2: out partials = msg @ We (K chunks of 256) — 384 blocks
    gemm_k<32, 32, 128, false><<<dim3(24, 8, 2), 128>>>(
        msg, We, outp, 256, INNER, D, D,
        256, (long)256 * D, (long)BU * D, EpiNone{});
    reduce_out_k<<<192, 256>>>(outp, rec, be, gam, out);
}